// round 9
// baseline (speedup 1.0000x reference)
#include <cuda_runtime.h>
#include <math.h>

// Scratch (allocation-free).
__device__ float g_hp[8192];          // [bc][p]      h-bin means
__device__ float g_vp_part[131072];   // [bc][p][q]   per-h-bin w partial sums
__device__ float g_sig[131072];       // [bc][p][q]   precomputed sigmoids

// ---------------------------------------------------------------------------
// Kernel 1: strip pooling for ONE batch. Grid 1024 = 64 planes x 16 h-bins,
// 128 threads. Default cache policy: allocate in L2 so the gate (running
// ~1-2 batches behind on another stream) hits these lines.
// ---------------------------------------------------------------------------
__global__ void __launch_bounds__(128) sp_pool_kernel(const float* __restrict__ x, int b) {
    const int blk = blockIdx.x;            // 0..1023
    const int bc  = b * 64 + (blk >> 4);
    const int p   = blk & 15;
    const float4* __restrict__ tile =
        reinterpret_cast<const float4*>(x + (size_t)bc * 65536) + p * 1024;

    const int t    = threadIdx.x;
    const int half = t >> 6;
    const int cg   = t & 63;
    const int lane = t & 31;
    const int wrp  = t >> 5;

    float4 v[8];
#pragma unroll
    for (int j = 0; j < 8; ++j)
        v[j] = tile[(half * 8 + j) * 64 + cg];

    float acc = 0.f;
#pragma unroll
    for (int j = 0; j < 8; ++j)
        acc += (v[j].x + v[j].y) + (v[j].z + v[j].w);

    __shared__ float s_h[4];
    __shared__ float s_w[16];
    if (t < 16) s_w[t] = 0.f;
    __syncthreads();

    float wsum = acc;
    wsum += __shfl_down_sync(0xffffffffu, wsum, 2);
    wsum += __shfl_down_sync(0xffffffffu, wsum, 1);
    if ((lane & 3) == 0) atomicAdd(&s_w[cg >> 2], wsum);

    float hsum = acc;
#pragma unroll
    for (int off = 16; off; off >>= 1)
        hsum += __shfl_down_sync(0xffffffffu, hsum, off);
    if (lane == 0) s_h[wrp] = hsum;
    __syncthreads();

    if (t == 0)
        g_hp[bc * 16 + p] = (s_h[0] + s_h[1] + s_h[2] + s_h[3]) * (1.0f / 4096.0f);
    if (t < 16)
        g_vp_part[bc * 256 + p * 16 + t] = s_w[t];
}

// ---------------------------------------------------------------------------
// Kernel 2: full mix chain + sigmoid table for ONE batch. 1 block x 1024 thr.
// Runs on a side stream, fully hidden by the pool/gate pipeline.
// ---------------------------------------------------------------------------
__global__ void __launch_bounds__(1024) sp_mix_kernel(
    int b,
    const float* __restrict__ Wh, const float* __restrict__ bh,
    const float* __restrict__ Wv, const float* __restrict__ bv,
    const float* __restrict__ Wf, const float* __restrict__ bf,
    const float* __restrict__ hg, const float* __restrict__ hb,
    const float* __restrict__ hm, const float* __restrict__ hv,
    const float* __restrict__ vg, const float* __restrict__ vb,
    const float* __restrict__ vm, const float* __restrict__ vv,
    const float* __restrict__ fg, const float* __restrict__ fb,
    const float* __restrict__ fm, const float* __restrict__ fvr)
{
    __shared__ float s_a[1024];    // hp  -> fh
    __shared__ float s_b[1024];    // vp  -> fv
    __shared__ float s_hpn[1024];
    __shared__ float s_vpn[1024];

    const int t = threadIdx.x;     // 0..1023
    const int o = t >> 4, p = t & 15;

    s_a[t] = g_hp[b * 1024 + t];
    {
        const float* vp = g_vp_part + (size_t)(b * 64 + o) * 256 + p;
        float sum = 0.f;
#pragma unroll
        for (int pp = 0; pp < 16; ++pp) sum += vp[pp * 16];
        s_b[t] = sum * (1.0f / 4096.0f);
    }
    __syncthreads();

    {
        float ah = 0.f, av = 0.f;
#pragma unroll 8
        for (int c = 0; c < 64; ++c) {
            ah += Wh[o * 64 + c] * s_a[c * 16 + p];
            av += Wv[o * 64 + c] * s_b[c * 16 + p];
        }
        const float invh = hg[o] * rsqrtf(hv[o] + 1e-5f);
        const float invv = vg[o] * rsqrtf(vv[o] + 1e-5f);
        s_hpn[t] = (ah + bh[o]) * invh + (hb[o] - hm[o] * invh);
        s_vpn[t] = (av + bv[o]) * invv + (vb[o] - vm[o] * invv);
    }
    __syncthreads();

    {
        float ah = 0.f, av = 0.f;
#pragma unroll 8
        for (int c = 0; c < 64; ++c) {
            ah += Wf[o * 128 + c]      * s_hpn[c * 16 + p];
            av += Wf[o * 128 + 64 + c] * s_vpn[c * 16 + p];
        }
        const float invf = fg[o] * rsqrtf(fvr[o] + 1e-5f);
        s_a[t] = ah * invf;                                       // fh[o][p]
        s_b[t] = (av + bf[o]) * invf + (fb[o] - fm[o] * invf);    // fv[o][q]
    }
    __syncthreads();

#pragma unroll
    for (int k = 0; k < 16; ++k) {
        const int i  = k * 1024 + t;
        const int ch = i >> 8;
        const int pp = (i >> 4) & 15;
        const int qq = i & 15;
        const float z = s_a[ch * 16 + pp] + s_b[ch * 16 + qq];
        g_sig[(size_t)(b * 64 + ch) * 256 + pp * 16 + qq] =
            1.0f / (1.0f + expf(-z));
    }
}

// ---------------------------------------------------------------------------
// Kernel 3: gate for ONE batch. Grid 512 = 64 planes x 8 chunks (32 rows).
// Reads x(b) (L2-hot from pool_b) with .cs; stores write-through so output
// never allocates in L2 (protects upcoming batches' x lines).
// ---------------------------------------------------------------------------
__global__ void __launch_bounds__(256) sp_gate_kernel(
    const float4* __restrict__ x4, float4* __restrict__ out4, int b)
{
    const int plane = b * 64 + (blockIdx.x >> 3);
    const int chunk = blockIdx.x & 7;
    const size_t base = (size_t)plane * 16384 + (size_t)chunk * 2048;

    const int t  = threadIdx.x;
    const int wb = (t & 63) >> 2;

    const float* __restrict__ sig = g_sig + plane * 256 + chunk * 32;
    const float s0 = __ldg(&sig[wb]);
    const float s1 = __ldg(&sig[16 + wb]);

#pragma unroll
    for (int j = 0; j < 8; ++j) {
        const size_t idx = base + j * 256 + t;
        float4 v = __ldcs(&x4[idx]);
        const float s = (j < 4) ? s0 : s1;
        v.x *= s; v.y *= s; v.z *= s; v.w *= s;
        __stwt(&out4[idx], v);
    }
}

// ---------------------------------------------------------------------------
// Host: per-batch pipeline across 3 streams.
//   s0 (launch stream): pool_0..pool_7 back-to-back
//   sMix:  mix_b  after pool_b   (event)
//   sGate: gate_b after mix_b    (event)
// Streams/events created once on the FIRST call (the correctness run, which
// is not captured); the capture call only records launches + event edges,
// which fork and rejoin the origin stream (valid capture topology).
// ---------------------------------------------------------------------------
extern "C" void kernel_launch(void* const* d_in, const int* in_sizes, int n_in,
                              void* d_out, int out_size)
{
    const float* x  = (const float*)d_in[0];
    const float* Wh = (const float*)d_in[1];
    const float* bh = (const float*)d_in[2];
    const float* Wv = (const float*)d_in[3];
    const float* bv = (const float*)d_in[4];
    const float* Wf = (const float*)d_in[5];
    const float* bf = (const float*)d_in[6];
    const float* hg = (const float*)d_in[7];
    const float* hb = (const float*)d_in[8];
    const float* hm = (const float*)d_in[9];
    const float* hv = (const float*)d_in[10];
    const float* vg = (const float*)d_in[11];
    const float* vb = (const float*)d_in[12];
    const float* vm = (const float*)d_in[13];
    const float* vv = (const float*)d_in[14];
    const float* fg = (const float*)d_in[15];
    const float* fb = (const float*)d_in[16];
    const float* fm = (const float*)d_in[17];
    const float* fv = (const float*)d_in[18];

    static cudaStream_t sMix = nullptr, sGate = nullptr;
    static cudaEvent_t  evPool[8], evMix[8], evJoin;
    if (sMix == nullptr) {
        cudaStreamCreateWithFlags(&sMix,  cudaStreamNonBlocking);
        cudaStreamCreateWithFlags(&sGate, cudaStreamNonBlocking);
        for (int b = 0; b < 8; ++b) {
            cudaEventCreateWithFlags(&evPool[b], cudaEventDisableTiming);
            cudaEventCreateWithFlags(&evMix[b],  cudaEventDisableTiming);
        }
        cudaEventCreateWithFlags(&evJoin, cudaEventDisableTiming);
    }

    for (int b = 0; b < 8; ++b) {
        sp_pool_kernel<<<1024, 128, 0, 0>>>(x, b);
        cudaEventRecord(evPool[b], 0);

        cudaStreamWaitEvent(sMix, evPool[b], 0);
        sp_mix_kernel<<<1, 1024, 0, sMix>>>(b, Wh, bh, Wv, bv, Wf, bf,
                                            hg, hb, hm, hv,
                                            vg, vb, vm, vv,
                                            fg, fb, fm, fv);
        cudaEventRecord(evMix[b], sMix);

        cudaStreamWaitEvent(sGate, evMix[b], 0);
        sp_gate_kernel<<<512, 256, 0, sGate>>>((const float4*)x, (float4*)d_out, b);
    }

    // Rejoin all forked work into the launch stream.
    cudaEventRecord(evJoin, sGate);
    cudaStreamWaitEvent(0, evJoin, 0);
}

// round 10
// speedup vs baseline: 2.7880x; 2.7880x over previous
#include <cuda_runtime.h>
#include <math.h>

// Scratch (allocation-free).
__device__ float g_hp[8192];          // [bc][p]      h-bin means
__device__ float g_vp_part[131072];   // [bc][p][q]   per-h-bin w partial sums
__device__ float g_fh[8192];          // [b][c][p]
__device__ float g_fv[8192];          // [b][c][q]

// Planes [0, PIN_PLANES) of x are kept L2-resident (96MB < 126MB L2);
// the rest stream through with evict_first.
#define PIN_PLANES 384

__device__ __forceinline__ float4 ld4_pol(const float4* p, unsigned long long pol) {
    float4 v;
    asm volatile("ld.global.L2::cache_hint.v4.f32 {%0,%1,%2,%3}, [%4], %5;"
                 : "=f"(v.x), "=f"(v.y), "=f"(v.z), "=f"(v.w)
                 : "l"(p), "l"(pol));
    return v;
}
__device__ __forceinline__ unsigned long long pol_for_plane(int bc) {
    unsigned long long pl, pf;
    asm("createpolicy.fractional.L2::evict_last.b64 %0, 1.0;"  : "=l"(pl));
    asm("createpolicy.fractional.L2::evict_first.b64 %0, 1.0;" : "=l"(pf));
    return (bc < PIN_PLANES) ? pl : pf;
}

// ---------------------------------------------------------------------------
// Kernel 1: strip pooling. One block per (plane, h-bin): grid 8192, 128 thr.
// ---------------------------------------------------------------------------
__global__ void __launch_bounds__(128) sp_pool_kernel(const float* __restrict__ x) {
    const int blk = blockIdx.x;           // 0..8191
    const int bc  = blk >> 4;
    const int p   = blk & 15;
    const float4* __restrict__ tile =
        reinterpret_cast<const float4*>(x + (size_t)bc * 65536) + p * 1024;

    const int t    = threadIdx.x;
    const int half = t >> 6;
    const int cg   = t & 63;
    const int lane = t & 31;
    const int wrp  = t >> 5;

    const unsigned long long pol = pol_for_plane(bc);

    float4 v[8];
#pragma unroll
    for (int j = 0; j < 8; ++j)
        v[j] = ld4_pol(&tile[(half * 8 + j) * 64 + cg], pol);

    float acc = 0.f;
#pragma unroll
    for (int j = 0; j < 8; ++j)
        acc += (v[j].x + v[j].y) + (v[j].z + v[j].w);

    __shared__ float s_h[4];
    __shared__ float s_w[16];
    if (t < 16) s_w[t] = 0.f;
    __syncthreads();

    float wsum = acc;
    wsum += __shfl_down_sync(0xffffffffu, wsum, 2);
    wsum += __shfl_down_sync(0xffffffffu, wsum, 1);
    if ((lane & 3) == 0) atomicAdd(&s_w[cg >> 2], wsum);

    float hsum = acc;
#pragma unroll
    for (int off = 16; off; off >>= 1)
        hsum += __shfl_down_sync(0xffffffffu, hsum, off);
    if (lane == 0) s_h[wrp] = hsum;
    __syncthreads();

    if (t == 0)
        g_hp[bc * 16 + p] = (s_h[0] + s_h[1] + s_h[2] + s_h[3]) * (1.0f / 4096.0f);
    if (t < 16)
        g_vp_part[bc * 256 + p * 16 + t] = s_w[t];
}

// ---------------------------------------------------------------------------
// Kernel 2: full mix chain. 8 blocks x 1024 threads; one (o,p) per thread at
// each stage, staged through shared memory. Outputs g_fh, g_fv.
// ---------------------------------------------------------------------------
__global__ void __launch_bounds__(1024) sp_mix_kernel(
    const float* __restrict__ Wh, const float* __restrict__ bh,
    const float* __restrict__ Wv, const float* __restrict__ bv,
    const float* __restrict__ Wf, const float* __restrict__ bf,
    const float* __restrict__ hg, const float* __restrict__ hb,
    const float* __restrict__ hm, const float* __restrict__ hv,
    const float* __restrict__ vg, const float* __restrict__ vb,
    const float* __restrict__ vm, const float* __restrict__ vv,
    const float* __restrict__ fg, const float* __restrict__ fb,
    const float* __restrict__ fm, const float* __restrict__ fvr)
{
    __shared__ float s_a[1024];    // hp
    __shared__ float s_b[1024];    // vp
    __shared__ float s_hpn[1024];
    __shared__ float s_vpn[1024];

    const int b = blockIdx.x;
    const int t = threadIdx.x;     // 0..1023
    const int o = t >> 4, p = t & 15;

    s_a[t] = g_hp[b * 1024 + t];
    {
        const float* vp = g_vp_part + (size_t)(b * 64 + o) * 256 + p;
        float sum = 0.f;
#pragma unroll
        for (int pp = 0; pp < 16; ++pp) sum += vp[pp * 16];
        s_b[t] = sum * (1.0f / 4096.0f);
    }
    __syncthreads();

    {
        float ah = 0.f, av = 0.f;
#pragma unroll 8
        for (int c = 0; c < 64; ++c) {
            ah += Wh[o * 64 + c] * s_a[c * 16 + p];
            av += Wv[o * 64 + c] * s_b[c * 16 + p];
        }
        const float invh = hg[o] * rsqrtf(hv[o] + 1e-5f);
        const float invv = vg[o] * rsqrtf(vv[o] + 1e-5f);
        s_hpn[t] = (ah + bh[o]) * invh + (hb[o] - hm[o] * invh);
        s_vpn[t] = (av + bv[o]) * invv + (vb[o] - vm[o] * invv);
    }
    __syncthreads();

    {
        float ah = 0.f, av = 0.f;
#pragma unroll 8
        for (int c = 0; c < 64; ++c) {
            ah += Wf[o * 128 + c]      * s_hpn[c * 16 + p];
            av += Wf[o * 128 + 64 + c] * s_vpn[c * 16 + p];
        }
        const float invf = fg[o] * rsqrtf(fvr[o] + 1e-5f);
        g_fh[b * 1024 + t] = ah * invf;
        g_fv[b * 1024 + t] = (av + bf[o]) * invf + (fb[o] - fm[o] * invf);
    }
}

// ---------------------------------------------------------------------------
// Kernel 3: out = sigmoid(fh[h>>4] + fv[w>>4]) * x. Sigmoid computed inline
// (2 ldg + 2 MUFU exp per thread - free under DRAM bound). Reverse block
// order: unpinned planes (511..384) first, pinned planes (383..0, still
// L2-resident from pool) last. Stores write-through.
// ---------------------------------------------------------------------------
__global__ void __launch_bounds__(256) sp_gate_kernel(
    const float4* __restrict__ x4, float4* __restrict__ out4)
{
    const int rblk  = 4095 - blockIdx.x;
    const int plane = rblk >> 3;
    const int chunk = rblk & 7;          // 32-row chunk = 2 h-bins
    const size_t base = (size_t)plane * 16384 + (size_t)chunk * 2048;

    const int t  = threadIdx.x;
    const int wb = (t & 63) >> 2;

    const float fvq = __ldg(&g_fv[plane * 16 + wb]);
    const float z0  = __ldg(&g_fh[plane * 16 + chunk * 2])     + fvq;
    const float z1  = __ldg(&g_fh[plane * 16 + chunk * 2 + 1]) + fvq;
    const float s0  = 1.0f / (1.0f + __expf(-z0));
    const float s1  = 1.0f / (1.0f + __expf(-z1));

    const unsigned long long pol = pol_for_plane(plane);

#pragma unroll
    for (int j = 0; j < 8; ++j) {
        const size_t idx = base + j * 256 + t;
        float4 v = ld4_pol(&x4[idx], pol);
        const float s = (j < 4) ? s0 : s1;
        v.x *= s; v.y *= s; v.z *= s; v.w *= s;
        __stwt(&out4[idx], v);
    }
}

// ---------------------------------------------------------------------------
extern "C" void kernel_launch(void* const* d_in, const int* in_sizes, int n_in,
                              void* d_out, int out_size)
{
    const float* x  = (const float*)d_in[0];
    const float* Wh = (const float*)d_in[1];
    const float* bh = (const float*)d_in[2];
    const float* Wv = (const float*)d_in[3];
    const float* bv = (const float*)d_in[4];
    const float* Wf = (const float*)d_in[5];
    const float* bf = (const float*)d_in[6];
    const float* hg = (const float*)d_in[7];
    const float* hb = (const float*)d_in[8];
    const float* hm = (const float*)d_in[9];
    const float* hv = (const float*)d_in[10];
    const float* vg = (const float*)d_in[11];
    const float* vb = (const float*)d_in[12];
    const float* vm = (const float*)d_in[13];
    const float* vv = (const float*)d_in[14];
    const float* fg = (const float*)d_in[15];
    const float* fb = (const float*)d_in[16];
    const float* fm = (const float*)d_in[17];
    const float* fv = (const float*)d_in[18];

    sp_pool_kernel<<<8192, 128>>>(x);
    sp_mix_kernel<<<8, 1024>>>(Wh, bh, Wv, bv, Wf, bf,
                               hg, hb, hm, hv,
                               vg, vb, vm, vv,
                               fg, fb, fm, fv);
    sp_gate_kernel<<<4096, 256>>>((const float4*)x, (float4*)d_out);
}